// round 16
// baseline (speedup 1.0000x reference)
#include <cuda_runtime.h>
#include <cuda_bf16.h>
#include <math.h>
#include <cstdint>

#define NB 2
#define TT 2048
#define BT 4096      // NB*TT
#define NH 16
#define HD 64
#define DM 1024
#define DL 256
#define BHN 32       // NB*NH
#define LOG2E 1.4426950408889634f

// ---------------- static device scratch ----------------
__device__ float g_q  [BT * DM];
__device__ float g_kv [BT * 2 * DM];
__device__ float g_qh [BHN * TT * HD];
__device__ float g_kh [BHN * TT * HD];
__device__ float g_mk [BHN * HD];
__device__ float g_mv [BHN * HD];
__device__ float g_bias[2 * TT - 1];
__device__ double g_invf[32];

__device__ __nv_bfloat16 g_xhi [BT * DM],  g_xlo [BT * DM];
__device__ __nv_bfloat16 g_kvdhi[BT * DL], g_kvdlo[BT * DL];
__device__ __nv_bfloat16 g_ctxhi[BT * DM], g_ctxlo[BT * DM];
__device__ __nv_bfloat16 g_wqhi [DM * DM],     g_wqlo [DM * DM];
__device__ __nv_bfloat16 g_wkdhi[DL * DM],     g_wkdlo[DL * DM];
__device__ __nv_bfloat16 g_wkuhi[2 * DM * DL], g_wkulo[2 * DM * DL];
__device__ __nv_bfloat16 g_wohi [DM * DM],     g_wolo [DM * DM];
__device__ __nv_bfloat16 g_qbhi[BHN * TT * HD], g_qblo[BHN * TT * HD];   // [bh][t][d]
__device__ __nv_bfloat16 g_kbhi[BHN * TT * HD], g_kblo[BHN * TT * HD];   // [bh][t][d]
__device__ __nv_bfloat16 g_vbhi[BHN * TT * HD], g_vblo[BHN * TT * HD];   // [bh][t][d]

// ---------------- PTX helpers (sm_80-compatible only) ----------------
__device__ __forceinline__ uint32_t smem_u32(const void* p) {
    uint32_t a;
    asm("{ .reg .u64 t; cvta.to.shared.u64 t, %1; cvt.u32.u64 %0, t; }" : "=r"(a) : "l"(p));
    return a;
}
__device__ __forceinline__ void cp16(uint32_t dst, const void* src) {
    asm volatile("cp.async.cg.shared.global [%0], [%1], 16;" :: "r"(dst), "l"(src));
}
#define CP_COMMIT() asm volatile("cp.async.commit_group;" ::: "memory")
#define CP_WAIT(n)  asm volatile("cp.async.wait_group %0;" :: "n"(n) : "memory")

__device__ __forceinline__ void ldsm4(uint32_t* r, uint32_t addr) {
    asm volatile("ldmatrix.sync.aligned.m8n8.x4.shared.b16 {%0,%1,%2,%3}, [%4];"
        : "=r"(r[0]), "=r"(r[1]), "=r"(r[2]), "=r"(r[3]) : "r"(addr));
}
__device__ __forceinline__ void ldsm4t(uint32_t* r, uint32_t addr) {
    asm volatile("ldmatrix.sync.aligned.m8n8.x4.trans.shared.b16 {%0,%1,%2,%3}, [%4];"
        : "=r"(r[0]), "=r"(r[1]), "=r"(r[2]), "=r"(r[3]) : "r"(addr));
}
__device__ __forceinline__ void mma_bf16(float* d, const uint32_t* a, uint32_t b0, uint32_t b1) {
    asm volatile("mma.sync.aligned.m16n8k16.row.col.f32.bf16.bf16.f32 "
        "{%0,%1,%2,%3},{%4,%5,%6,%7},{%8,%9},{%0,%1,%2,%3};"
        : "+f"(d[0]), "+f"(d[1]), "+f"(d[2]), "+f"(d[3])
        : "r"(a[0]), "r"(a[1]), "r"(a[2]), "r"(a[3]), "r"(b0), "r"(b1));
}
__device__ __forceinline__ uint32_t pack_bf2(float a, float b) {
    __nv_bfloat162 h = __float22bfloat162_rn(make_float2(a, b));
    return *reinterpret_cast<uint32_t*>(&h);
}

// ---------------- conversion kernels ----------------
__global__ void conv_split(const float* __restrict__ in, __nv_bfloat16* __restrict__ hi,
                           __nv_bfloat16* __restrict__ lo, int n) {
    int i = (blockIdx.x * blockDim.x + threadIdx.x) * 4;
    if (i >= n) return;
    float4 v = *(const float4*)(in + i);
    float f[4] = {v.x, v.y, v.z, v.w};
    __nv_bfloat16 h[4], l[4];
    #pragma unroll
    for (int j = 0; j < 4; j++) {
        h[j] = __float2bfloat16_rn(f[j]);
        l[j] = __float2bfloat16_rn(f[j] - __bfloat162float(h[j]));
    }
    *(__nv_bfloat162*)(hi + i)     = __nv_bfloat162(h[0], h[1]);
    *(__nv_bfloat162*)(hi + i + 2) = __nv_bfloat162(h[2], h[3]);
    *(__nv_bfloat162*)(lo + i)     = __nv_bfloat162(l[0], l[1]);
    *(__nv_bfloat162*)(lo + i + 2) = __nv_bfloat162(l[2], l[3]);
}

// W[K,N] -> hiT/loT[N,K]
__global__ void transpose_split(const float* __restrict__ in, __nv_bfloat16* __restrict__ hiT,
                                __nv_bfloat16* __restrict__ loT, int K, int N) {
    __shared__ float t[32][33];
    int n0 = blockIdx.x * 32, k0 = blockIdx.y * 32;
    int tx = threadIdx.x, ty = threadIdx.y;  // 32 x 8
    #pragma unroll
    for (int j = 0; j < 32; j += 8)
        t[ty + j][tx] = in[(size_t)(k0 + ty + j) * N + n0 + tx];
    __syncthreads();
    #pragma unroll
    for (int j = 0; j < 32; j += 8) {
        float f = t[tx][ty + j];
        __nv_bfloat16 h = __float2bfloat16_rn(f);
        __nv_bfloat16 l = __float2bfloat16_rn(f - __bfloat162float(h));
        hiT[(size_t)(n0 + ty + j) * K + k0 + tx] = h;
        loT[(size_t)(n0 + ty + j) * K + k0 + tx] = l;
    }
}

// ---------------- mma.sync GEMM mainloop: BK=32, 4-stage ring, sync per 2 iters ----------------
#define PITCH 80
#define TILEB 10240
#define STAGEB 40960
#define GNSTG 4

#define GEMM_MAINLOOP(Ahi, Alo, Bhi, Blo, K)                                              \
    float acc[2][8][4];                                                                   \
    _Pragma("unroll")                                                                     \
    for (int a_ = 0; a_ < 2; a_++)                                                        \
        _Pragma("unroll")                                                                 \
        for (int b_ = 0; b_ < 8; b_++)                                                    \
            _Pragma("unroll")                                                             \
            for (int c_ = 0; c_ < 4; c_++) acc[a_][b_][c_] = 0.f;                         \
    int lrow = tid >> 1;                                                                  \
    int lc0 = (tid & 1) * 2;                                                              \
    auto load_stage = [&](int kb) {                                                       \
        int st = kb & (GNSTG - 1);                                                        \
        size_t gA = (size_t)(m0 + lrow) * (K) + kb * 32 + lc0 * 8;                        \
        size_t gB = (size_t)(n0 + lrow) * (K) + kb * 32 + lc0 * 8;                        \
        uint32_t so = smb + st * STAGEB + lrow * PITCH + lc0 * 16;                        \
        cp16(so,                  Ahi + gA); cp16(so + 16,              Ahi + gA + 8);    \
        cp16(so + TILEB,          Alo + gA); cp16(so + TILEB + 16,      Alo + gA + 8);    \
        cp16(so + 2 * TILEB,      Bhi + gB); cp16(so + 2 * TILEB + 16,  Bhi + gB + 8);    \
        cp16(so + 3 * TILEB,      Blo + gB); cp16(so + 3 * TILEB + 16,  Blo + gB + 8);    \
    };                                                                                    \
    auto body = [&](int kb) {                                                             \
        uint32_t base = smb + (kb & (GNSTG - 1)) * STAGEB;                                \
        _Pragma("unroll")                                                                 \
        for (int s16 = 0; s16 < 2; s16++) {                                               \
            uint32_t koff = s16 * 32;                                                     \
            uint32_t ah[2][4], al[2][4];                                                  \
            _Pragma("unroll")                                                             \
            for (int mf = 0; mf < 2; mf++) {                                              \
                uint32_t ad = base + (wm + mf * 16 + (lane & 15)) * PITCH + koff + (lane >> 4) * 16; \
                ldsm4(ah[mf], ad);                                                        \
                ldsm4(al[mf], ad + TILEB);                                                \
            }                                                                             \
            uint32_t bhf[8][2], blf[8][2];                                                \
            _Pragma("unroll")                                                             \
            for (int nb = 0; nb < 4; nb++) {                                              \
                uint32_t bd = base + 2 * TILEB + (wn + nb * 16 + (lane & 15)) * PITCH + koff + (lane >> 4) * 16; \
                uint32_t r[4];                                                            \
                ldsm4(r, bd);                                                             \
                bhf[2 * nb][0] = r[0]; bhf[2 * nb][1] = r[2];                             \
                bhf[2 * nb + 1][0] = r[1]; bhf[2 * nb + 1][1] = r[3];                     \
                ldsm4(r, bd + TILEB);                                                     \
                blf[2 * nb][0] = r[0]; blf[2 * nb][1] = r[2];                             \
                blf[2 * nb + 1][0] = r[1]; blf[2 * nb + 1][1] = r[3];                     \
            }                                                                             \
            _Pragma("unroll")                                                             \
            for (int mf = 0; mf < 2; mf++)                                                \
                _Pragma("unroll")                                                         \
                for (int nf = 0; nf < 8; nf++) {                                          \
                    mma_bf16(acc[mf][nf], ah[mf], bhf[nf][0], bhf[nf][1]);                \
                    mma_bf16(acc[mf][nf], ah[mf], blf[nf][0], blf[nf][1]);                \
                    mma_bf16(acc[mf][nf], al[mf], bhf[nf][0], bhf[nf][1]);                \
                }                                                                         \
        }                                                                                 \
    };                                                                                    \
    const int NBK = (K) >> 5;  /* even for all uses */                                    \
    load_stage(0); CP_COMMIT();                                                           \
    load_stage(1); CP_COMMIT();                                                           \
    for (int kb = 0; kb < NBK; kb += 2) {                                                 \
        __syncthreads();                                                                  \
        if (kb + 2 < NBK) { load_stage(kb + 2); CP_COMMIT(); }                            \
        if (kb + 3 < NBK) { load_stage(kb + 3); CP_COMMIT(); }                            \
        if (kb + 3 < NBK)      { CP_WAIT(2); }                                           \
        else if (kb + 2 < NBK) { CP_WAIT(1); }                                           \
        else                   { CP_WAIT(0); }                                           \
        body(kb);                                                                         \
        body(kb + 1);                                                                     \
    }

__global__ void __launch_bounds__(256, 1)
gemm_mma(const __nv_bfloat16* __restrict__ Ahi, const __nv_bfloat16* __restrict__ Alo,
         const __nv_bfloat16* __restrict__ Bhi, const __nv_bfloat16* __restrict__ Blo,
         const float* __restrict__ bias, float* __restrict__ C, int M, int N, int K) {
    extern __shared__ __align__(128) char sm[];
    uint32_t smb = smem_u32(sm);
    int tid = threadIdx.x, lane = tid & 31, wid = tid >> 5;
    int m0 = blockIdx.y * 128, n0 = blockIdx.x * 128;
    int wm = (wid & 3) * 32, wn = (wid >> 2) * 64;

    GEMM_MAINLOOP(Ahi, Alo, Bhi, Blo, K)

    #pragma unroll
    for (int mf = 0; mf < 2; mf++) {
        int r0 = m0 + wm + mf * 16 + (lane >> 2);
        #pragma unroll
        for (int nf = 0; nf < 8; nf++) {
            int c0 = n0 + wn + nf * 8 + (lane & 3) * 2;
            float2 v0, v1;
            v0.x = acc[mf][nf][0] + bias[c0];
            v0.y = acc[mf][nf][1] + bias[c0 + 1];
            v1.x = acc[mf][nf][2] + bias[c0];
            v1.y = acc[mf][nf][3] + bias[c0 + 1];
            *(float2*)&C[(size_t)r0 * N + c0]       = v0;
            *(float2*)&C[(size_t)(r0 + 8) * N + c0] = v1;
        }
    }
}

// same mainloop, bf16-split output (for KV-down projection)
__global__ void __launch_bounds__(256, 1)
gemm_mma_split(const __nv_bfloat16* __restrict__ Ahi, const __nv_bfloat16* __restrict__ Alo,
               const __nv_bfloat16* __restrict__ Bhi, const __nv_bfloat16* __restrict__ Blo,
               const float* __restrict__ bias, __nv_bfloat16* __restrict__ Chi,
               __nv_bfloat16* __restrict__ Clo, int M, int N, int K) {
    extern __shared__ __align__(128) char sm[];
    uint32_t smb = smem_u32(sm);
    int tid = threadIdx.x, lane = tid & 31, wid = tid >> 5;
    int m0 = blockIdx.y * 128, n0 = blockIdx.x * 128;
    int wm = (wid & 3) * 32, wn = (wid >> 2) * 64;

    GEMM_MAINLOOP(Ahi, Alo, Bhi, Blo, K)

    #pragma unroll
    for (int mf = 0; mf < 2; mf++) {
        int r0 = m0 + wm + mf * 16 + (lane >> 2);
        #pragma unroll
        for (int nf = 0; nf < 8; nf++) {
            int c0 = n0 + wn + nf * 8 + (lane & 3) * 2;
            #pragma unroll
            for (int half = 0; half < 2; half++) {
                float f0 = acc[mf][nf][half * 2]     + bias[c0];
                float f1 = acc[mf][nf][half * 2 + 1] + bias[c0 + 1];
                __nv_bfloat16 h0 = __float2bfloat16_rn(f0), h1 = __float2bfloat16_rn(f1);
                __nv_bfloat16 l0 = __float2bfloat16_rn(f0 - __bfloat162float(h0));
                __nv_bfloat16 l1 = __float2bfloat16_rn(f1 - __bfloat162float(h1));
                size_t off = (size_t)(r0 + half * 8) * N + c0;
                *(__nv_bfloat162*)&Chi[off] = __nv_bfloat162(h0, h1);
                *(__nv_bfloat162*)&Clo[off] = __nv_bfloat162(l0, l1);
            }
        }
    }
}

// ---------------- bias table (pre-scaled by log2 e) + inv_freq table ----------------
__global__ void bias_table(float* __restrict__ bt) {
    int idx = blockIdx.x * blockDim.x + threadIdx.x;
    if (idx < 32)
        g_invf[idx] = pow(10000.0, -(double)idx / 32.0);
    if (idx < 2 * TT - 1) {
        float d = (float)(idx - (TT - 1));
        float ls = -0.1f * logf(fabsf(d) + 1.0f);
        float dec = expf(-fmaxf(d, 0.0f) * 0.01f);
        bt[idx] = (ls + logf(dec + 1e-9f)) * LOG2E;
    }
}

// ---------------- RoPE + transpose (+ bf16 splits q,k,v) ----------------
__global__ void rope_transpose(const float* __restrict__ q, const float* __restrict__ kv,
                               float* __restrict__ qh, float* __restrict__ kh,
                               __nv_bfloat16* __restrict__ qbhi, __nv_bfloat16* __restrict__ qblo,
                               __nv_bfloat16* __restrict__ kbhi, __nv_bfloat16* __restrict__ kblo,
                               __nv_bfloat16* __restrict__ vbhi, __nv_bfloat16* __restrict__ vblo) {
    int token = blockIdx.x;
    int b = token / TT, t = token % TT;
    int tid = threadIdx.x;
    int h = tid >> 5, i = tid & 31;

    float ang = (float)((double)t * g_invf[i]);
    float cf = cosf(ang);
    float sf = sinf(ang);

    size_t dst = ((size_t)(b * NH + h) * TT + t) * HD;
    {
        const float* src = q + (size_t)token * DM + h * HD;
        float x1 = src[i], x2 = src[i + 32];
        float r1 = x1 * cf - x2 * sf;
        float r2 = x1 * sf + x2 * cf;
        qh[dst + i]      = r1;
        qh[dst + i + 32] = r2;
        __nv_bfloat16 h1 = __float2bfloat16_rn(r1), h2 = __float2bfloat16_rn(r2);
        qbhi[dst + i] = h1;      qblo[dst + i]      = __float2bfloat16_rn(r1 - __bfloat162float(h1));
        qbhi[dst + i + 32] = h2; qblo[dst + i + 32] = __float2bfloat16_rn(r2 - __bfloat162float(h2));
    }
    {
        const float* src = kv + (size_t)token * (2 * DM) + h * (2 * HD);
        float x1 = src[i], x2 = src[i + 32];
        float r1 = x1 * cf - x2 * sf;
        float r2 = x1 * sf + x2 * cf;
        kh[dst + i]      = r1;
        kh[dst + i + 32] = r2;
        __nv_bfloat16 h1 = __float2bfloat16_rn(r1), h2 = __float2bfloat16_rn(r2);
        kbhi[dst + i] = h1;      kblo[dst + i]      = __float2bfloat16_rn(r1 - __bfloat162float(h1));
        kbhi[dst + i + 32] = h2; kblo[dst + i + 32] = __float2bfloat16_rn(r2 - __bfloat162float(h2));
        float v1 = src[64 + i], v2 = src[64 + i + 32];
        __nv_bfloat16 vh1 = __float2bfloat16_rn(v1), vh2 = __float2bfloat16_rn(v2);
        vbhi[dst + i] = vh1;      vblo[dst + i]      = __float2bfloat16_rn(v1 - __bfloat162float(vh1));
        vbhi[dst + i + 32] = vh2; vblo[dst + i + 32] = __float2bfloat16_rn(v2 - __bfloat162float(vh2));
    }
}

// ---------------- mean-pool (512 threads, 8-way t-split; v from bf16 split) ----------------
__global__ void mean_kv(const float* __restrict__ kh,
                        const __nv_bfloat16* __restrict__ vbhi, const __nv_bfloat16* __restrict__ vblo,
                        float* __restrict__ mk, float* __restrict__ mv) {
    __shared__ float sk[8][64], sv[8][64];
    int bh = blockIdx.x;
    int d = threadIdx.x & 63, grp = threadIdx.x >> 6;
    const float* kb = kh + (size_t)bh * TT * HD;
    const __nv_bfloat16* vbh = vbhi + (size_t)bh * TT * HD;
    const __nv_bfloat16* vbl = vblo + (size_t)bh * TT * HD;
    float a = 0.f, c = 0.f;
    int t0 = grp * (TT / 8), t1 = t0 + TT / 8;
    for (int t = t0; t < t1; t++) {
        a += kb[(size_t)t * HD + d];
        c += __bfloat162float(vbh[(size_t)t * HD + d]) + __bfloat162float(vbl[(size_t)t * HD + d]);
    }
    sk[grp][d] = a;
    sv[grp][d] = c;
    __syncthreads();
    if (grp == 0) {
        float ta = 0.f, tc = 0.f;
        #pragma unroll
        for (int g = 0; g < 8; g++) { ta += sk[g][d]; tc += sv[g][d]; }
        mk[bh * HD + d] = ta * (1.0f / TT);
        mv[bh * HD + d] = tc * (1.0f / TT);
    }
}

// ---------------- flash attention: BM=128 BN=64, 6-stage ring, sync per 2 iters ----------------
#define FPITCH 144
#define FTILE  (64 * FPITCH)   // 9216
#define FSTG   (4 * FTILE)     // 36864 per stage (Khi|Klo|Vhi|Vlo, all [t][d])
#define NSTG   6
__global__ void __launch_bounds__(256, 1)
flash_mma(const __nv_bfloat16* __restrict__ qbhi, const __nv_bfloat16* __restrict__ qblo,
          const __nv_bfloat16* __restrict__ kbhi, const __nv_bfloat16* __restrict__ kblo,
          const __nv_bfloat16* __restrict__ vbhi, const __nv_bfloat16* __restrict__ vblo,
          const float* __restrict__ bias_tab, const float* __restrict__ qh,
          const float* __restrict__ mk, const float* __restrict__ mv,
          __nv_bfloat16* __restrict__ ctxhi, __nv_bfloat16* __restrict__ ctxlo) {
    extern __shared__ __align__(128) char sm[];
    __shared__ float mks[64], mvs[64];
    uint32_t smb = smem_u32(sm);
    int tid = threadIdx.x, lane = tid & 31, wid = tid >> 5;
    int bh = blockIdx.y, q0 = blockIdx.x * 128;
    int b = bh >> 4, h = bh & 15;
    int wm = wid * 16;

    const __nv_bfloat16* qhB = qbhi + (size_t)bh * TT * HD;
    const __nv_bfloat16* qlB = qblo + (size_t)bh * TT * HD;
    const __nv_bfloat16* khB = kbhi + (size_t)bh * TT * HD;
    const __nv_bfloat16* klB = kblo + (size_t)bh * TT * HD;
    const __nv_bfloat16* vhB = vbhi + (size_t)bh * TT * HD;
    const __nv_bfloat16* vlB = vblo + (size_t)bh * TT * HD;

    if (tid < 64) mks[tid] = mk[bh * HD + tid];
    else if (tid < 128) mvs[tid - 64] = mv[bh * HD + tid - 64];

    // ---- stage Q (128 x 64 bf16 hi+lo) into stage-0 area, extract frags ----
    {
        int row = tid >> 1;
        int ch  = (tid & 1) * 4;
        size_t g = (size_t)(q0 + row) * HD + ch * 8;
        uint32_t so = smb + row * FPITCH + ch * 16;
        #pragma unroll
        for (int c = 0; c < 4; c++) {
            cp16(so + c * 16,             qhB + g + c * 8);
            cp16(so + 2 * FTILE + c * 16, qlB + g + c * 8);
        }
    }
    CP_COMMIT(); CP_WAIT(0);
    __syncthreads();

    uint32_t qfh[4][4], qfl[4][4];
    #pragma unroll
    for (int ks = 0; ks < 4; ks++) {
        uint32_t ad = smb + (wm + (lane & 15)) * FPITCH + ks * 32 + (lane >> 4) * 16;
        ldsm4(qfh[ks], ad);
        ldsm4(qfl[ks], ad + 2 * FTILE);
    }
    __syncthreads();

    float o[8][4];
    #pragma unroll
    for (int i = 0; i < 8; i++)
        #pragma unroll
        for (int j = 0; j < 4; j++) o[i][j] = 0.f;
    float miA = -1e30f, miB = -1e30f, liA = 0.f, liB = 0.f;

    auto load_stage = [&](int k0, int st) {
        int row = tid >> 2;
        int ch  = (tid & 3) * 2;
        uint32_t so = smb + st * FSTG + row * FPITCH + ch * 16;
        size_t gk = (size_t)(k0 + row) * HD + ch * 8;
        cp16(so,             khB + gk); cp16(so + 16,             khB + gk + 8);
        cp16(so + FTILE,     klB + gk); cp16(so + FTILE + 16,     klB + gk + 8);
        cp16(so + 2 * FTILE, vhB + gk); cp16(so + 2 * FTILE + 16, vhB + gk + 8);
        cp16(so + 3 * FTILE, vlB + gk); cp16(so + 3 * FTILE + 16, vlB + gk + 8);
    };

    const float SC = 0.125f * LOG2E;
    const int NKB = TT / 64;
    int vrow = (lane & 7) + ((lane >> 4) & 1) * 8;
    int vcol = ((lane >> 3) & 1) * 16;

    auto body = [&](int kb) {
        int k0 = kb * 64;
        uint32_t kb_s = smb + (kb % NSTG) * FSTG;
        uint32_t vb_s = kb_s + 2 * FTILE;

        float s[8][4];
        #pragma unroll
        for (int i = 0; i < 8; i++)
            #pragma unroll
            for (int j = 0; j < 4; j++) s[i][j] = 0.f;

        #pragma unroll
        for (int ks = 0; ks < 4; ks++) {
            #pragma unroll
            for (int g = 0; g < 4; g++) {
                uint32_t ad = kb_s + (16 * g + (lane & 15)) * FPITCH + ks * 32 + (lane >> 4) * 16;
                uint32_t rh[4], rl[4];
                ldsm4(rh, ad);
                ldsm4(rl, ad + FTILE);
                mma_bf16(s[2 * g],     qfh[ks], rh[0], rh[2]);
                mma_bf16(s[2 * g],     qfh[ks], rl[0], rl[2]);
                mma_bf16(s[2 * g],     qfl[ks], rh[0], rh[2]);
                mma_bf16(s[2 * g + 1], qfh[ks], rh[1], rh[3]);
                mma_bf16(s[2 * g + 1], qfh[ks], rl[1], rl[3]);
                mma_bf16(s[2 * g + 1], qfl[ks], rh[1], rh[3]);
            }
        }

        int rA = wm + (lane >> 2);
        const float* bp = bias_tab + (q0 - k0 + rA - (lane & 3) * 2 + (TT - 1));
        float rmaxA = -1e30f, rmaxB = -1e30f;
        #pragma unroll
        for (int nf = 0; nf < 8; nf++) {
            s[nf][0] = s[nf][0] * SC + __ldg(bp - 8 * nf);
            s[nf][1] = s[nf][1] * SC + __ldg(bp - 8 * nf - 1);
            s[nf][2] = s[nf][2] * SC + __ldg(bp - 8 * nf + 8);
            s[nf][3] = s[nf][3] * SC + __ldg(bp - 8 * nf + 7);
            rmaxA = fmaxf(rmaxA, fmaxf(s[nf][0], s[nf][1]));
            rmaxB = fmaxf(rmaxB, fmaxf(s[nf][2], s[nf][3]));
        }
        #pragma unroll
        for (int off = 1; off <= 2; off <<= 1) {
            rmaxA = fmaxf(rmaxA, __shfl_xor_sync(0xffffffffu, rmaxA, off));
            rmaxB = fmaxf(rmaxB, __shfl_xor_sync(0xffffffffu, rmaxB, off));
        }
        float mnA = fmaxf(miA, rmaxA), mnB = fmaxf(miB, rmaxB);
        float scA = exp2f(miA - mnA), scB = exp2f(miB - mnB);
        miA = mnA; miB = mnB;
        float rsA = 0.f, rsB = 0.f;
        #pragma unroll
        for (int nf = 0; nf < 8; nf++) {
            s[nf][0] = exp2f(s[nf][0] - mnA);
            s[nf][1] = exp2f(s[nf][1] - mnA);
            s[nf][2] = exp2f(s[nf][2] - mnB);
            s[nf][3] = exp2f(s[nf][3] - mnB);
            rsA += s[nf][0] + s[nf][1];
            rsB += s[nf][2] + s[nf][3];
        }
        #pragma unroll
        for (int off = 1; off <= 2; off <<= 1) {
            rsA += __shfl_xor_sync(0xffffffffu, rsA, off);
            rsB += __shfl_xor_sync(0xffffffffu, rsB, off);
        }
        liA = liA * scA + rsA;
        liB = liB * scB + rsB;
        #pragma unroll
        for (int i = 0; i < 8; i++) {
            o[i][0] *= scA; o[i][1] *= scA;
            o[i][2] *= scB; o[i][3] *= scB;
        }

        #pragma unroll
        for (int ks = 0; ks < 4; ks++) {
            uint32_t ah[4], al[4];
            {
                float* p0 = s[2 * ks];
                float* p1 = s[2 * ks + 1];
                ah[0] = pack_bf2(p0[0], p0[1]);
                ah[1] = pack_bf2(p0[2], p0[3]);
                ah[2] = pack_bf2(p1[0], p1[1]);
                ah[3] = pack_bf2(p1[2], p1[3]);
                __nv_bfloat162* h0 = (__nv_bfloat162*)&ah[0];
                __nv_bfloat162* h1 = (__nv_bfloat162*)&ah[1];
                __nv_bfloat162* h2 = (__nv_bfloat162*)&ah[2];
                __nv_bfloat162* h3 = (__nv_bfloat162*)&ah[3];
                al[0] = pack_bf2(p0[0] - __bfloat162float(h0->x), p0[1] - __bfloat162float(h0->y));
                al[1] = pack_bf2(p0[2] - __bfloat162float(h1->x), p0[3] - __bfloat162float(h1->y));
                al[2] = pack_bf2(p1[0] - __bfloat162float(h2->x), p1[1] - __bfloat162float(h2->y));
                al[3] = pack_bf2(p1[2] - __bfloat162float(h3->x), p1[3] - __bfloat162float(h3->y));
            }
            #pragma unroll
            for (int g = 0; g < 4; g++) {
                uint32_t ad = vb_s + (ks * 16 + vrow) * FPITCH + g * 32 + vcol;
                uint32_t rh[4], rl[4];
                ldsm4t(rh, ad);
                ldsm4t(rl, ad + FTILE);
                mma_bf16(o[2 * g],     ah, rh[0], rh[2]);
                mma_bf16(o[2 * g],     al, rh[0], rh[2]);
                mma_bf16(o[2 * g],     ah, rl[0], rl[2]);
                mma_bf16(o[2 * g + 1], ah, rh[1], rh[3]);
                mma_bf16(o[2 * g + 1], al, rh[1], rh[3]);
                mma_bf16(o[2 * g + 1], ah, rl[1], rl[3]);
            }
        }
    };

    // prologue: stages 0..3
    load_stage(0, 0);       CP_COMMIT();
    load_stage(64, 1);      CP_COMMIT();
    load_stage(128, 2);     CP_COMMIT();
    load_stage(192, 3);     CP_COMMIT();

    for (int kb = 0; kb < NKB; kb += 2) {
        __syncthreads();
        if (kb + 4 < NKB) { load_stage((kb + 4) * 64, (kb + 4) % NSTG); CP_COMMIT(); }
        if (kb + 5 < NKB) { load_stage((kb + 5) * 64, (kb + 5) % NSTG); CP_COMMIT(); }
        if (kb + 6 <= NKB)      { CP_WAIT(4); }
        else if (kb + 4 <= NKB) { CP_WAIT(2); }
        else                    { CP_WAIT(0); }
        body(kb);
        body(kb + 1);
    }

    // ---- epilogue: normalize + fused infini + bf16 split write ----
    float invA = 1.0f / liA, invB = 1.0f / liB;
    int rowA = q0 + wm + (lane >> 2);
    const float* qrowA = qh + ((size_t)bh * TT + rowA) * HD;
    const float* qrowB = qrowA + 8 * HD;
    float dA = 0.f, dB = 0.f;
    #pragma unroll
    for (int j = 0; j < 16; j++) {
        int d = (lane & 3) * 16 + j;
        dA += qrowA[d] * mks[d];
        dB += qrowB[d] * mks[d];
    }
    #pragma unroll
    for (int off = 1; off <= 2; off <<= 1) {
        dA += __shfl_xor_sync(0xffffffffu, dA, off);
        dB += __shfl_xor_sync(0xffffffffu, dB, off);
    }
    float gA = 0.2f / (1.0f + expf(-dA));
    float gB = 0.2f / (1.0f + expf(-dB));

    #pragma unroll
    for (int nf = 0; nf < 8; nf++) {
        int c0 = 8 * nf + (lane & 3) * 2;
        float f[4];
        f[0] = o[nf][0] * invA + gA * mvs[c0];
        f[1] = o[nf][1] * invA + gA * mvs[c0 + 1];
        f[2] = o[nf][2] * invB + gB * mvs[c0];
        f[3] = o[nf][3] * invB + gB * mvs[c0 + 1];
        __nv_bfloat16 h0 = __float2bfloat16_rn(f[0]), h1 = __float2bfloat16_rn(f[1]);
        __nv_bfloat16 h2 = __float2bfloat16_rn(f[2]), h3 = __float2bfloat16_rn(f[3]);
        __nv_bfloat16 l0 = __float2bfloat16_rn(f[0] - __bfloat162float(h0));
        __nv_bfloat16 l1 = __float2bfloat16_rn(f[1] - __bfloat162float(h1));
        __nv_bfloat16 l2 = __float2bfloat16_rn(f[2] - __bfloat162float(h2));
        __nv_bfloat16 l3 = __float2bfloat16_rn(f[3] - __bfloat162float(h3));
        size_t oA = ((size_t)b * TT + rowA) * DM + h * HD + c0;
        size_t oB = ((size_t)b * TT + rowA + 8) * DM + h * HD + c0;
        *(__nv_bfloat162*)&ctxhi[oA] = __nv_bfloat162(h0, h1);
        *(__nv_bfloat162*)&ctxlo[oA] = __nv_bfloat162(l0, l1);
        *(__nv_bfloat162*)&ctxhi[oB] = __nv_bfloat162(h2, h3);
        *(__nv_bfloat162*)&ctxlo[oB] = __nv_bfloat162(l2, l3);
    }
}

// ---------------- launcher ----------------
extern "C" void kernel_launch(void* const* d_in, const int* in_sizes, int n_in,
                              void* d_out, int out_size) {
    const float* x   = (const float*)d_in[0];
    const float* Wq  = (const float*)d_in[1];
    const float* bq  = (const float*)d_in[2];
    const float* Wkd = (const float*)d_in[3];
    const float* bkd = (const float*)d_in[4];
    const float* Wku = (const float*)d_in[5];
    const float* bku = (const float*)d_in[6];
    const float* Wo  = (const float*)d_in[7];
    const float* bo  = (const float*)d_in[8];
    float* out = (float*)d_out;

    float *q, *kv, *qh, *kh, *mk, *mv, *bt;
    cudaGetSymbolAddress((void**)&q,   g_q);
    cudaGetSymbolAddress((void**)&kv,  g_kv);
    cudaGetSymbolAddress((void**)&qh,  g_qh);
    cudaGetSymbolAddress((void**)&kh,  g_kh);
    cudaGetSymbolAddress((void**)&mk,  g_mk);
    cudaGetSymbolAddress((void**)&mv,  g_mv);
    cudaGetSymbolAddress((void**)&bt,  g_bias);

    __nv_bfloat16 *xhi, *xlo, *kvdhi, *kvdlo, *ctxhi, *ctxlo;
    __nv_bfloat16 *wqhi, *wqlo, *wkdhi, *wkdlo, *wkuhi, *wkulo, *wohi, *wolo;
    __nv_bfloat16 *qbhi, *qblo, *kbhi, *kblo, *vbhi, *vblo;
    cudaGetSymbolAddress((void**)&xhi,   g_xhi);   cudaGetSymbolAddress((void**)&xlo,   g_xlo);
    cudaGetSymbolAddress((void**)&kvdhi, g_kvdhi); cudaGetSymbolAddress((void**)&kvdlo, g_kvdlo);
    cudaGetSymbolAddress((void**)&ctxhi, g_ctxhi); cudaGetSymbolAddress((void**)&ctxlo, g_ctxlo);
    cudaGetSymbolAddress((void**)&wqhi,  g_wqhi);  cudaGetSymbolAddress((void**)&wqlo,  g_wqlo);
    cudaGetSymbolAddress((void**)&wkdhi, g_wkdhi); cudaGetSymbolAddress((void**)&wkdlo, g_wkdlo);
    cudaGetSymbolAddress((void**)&wkuhi, g_wkuhi); cudaGetSymbolAddress((void**)&wkulo, g_wkulo);
    cudaGetSymbolAddress((void**)&wohi,  g_wohi);  cudaGetSymbolAddress((void**)&wolo,  g_wolo);
    cudaGetSymbolAddress((void**)&qbhi,  g_qbhi);  cudaGetSymbolAddress((void**)&qblo,  g_qblo);
    cudaGetSymbolAddress((void**)&kbhi,  g_kbhi);  cudaGetSymbolAddress((void**)&kblo,  g_kblo);
    cudaGetSymbolAddress((void**)&vbhi,  g_vbhi);  cudaGetSymbolAddress((void**)&vblo,  g_vblo);

    const int GEMM_SMEM = GNSTG * STAGEB;  // 163840
    cudaFuncSetAttribute(gemm_mma, cudaFuncAttributeMaxDynamicSharedMemorySize, GEMM_SMEM);
    cudaFuncSetAttribute(gemm_mma_split, cudaFuncAttributeMaxDynamicSharedMemorySize, GEMM_SMEM);
    const int FLASH_SMEM = NSTG * FSTG;    // 221184
    cudaFuncSetAttribute(flash_mma, cudaFuncAttributeMaxDynamicSharedMemorySize, FLASH_SMEM);

    dim3 t328(32, 8);

    bias_table<<<(2 * TT - 1 + 255) / 256, 256>>>(bt);

    transpose_split<<<dim3(DM / 32, DM / 32), t328>>>(Wq,  wqhi,  wqlo,  DM, DM);
    transpose_split<<<dim3(DL / 32, DM / 32), t328>>>(Wkd, wkdhi, wkdlo, DM, DL);
    transpose_split<<<dim3(2 * DM / 32, DL / 32), t328>>>(Wku, wkuhi, wkulo, DL, 2 * DM);
    transpose_split<<<dim3(DM / 32, DM / 32), t328>>>(Wo,  wohi,  wolo,  DM, DM);

    conv_split<<<(BT * DM / 4 + 255) / 256, 256>>>(x, xhi, xlo, BT * DM);

    gemm_mma<<<dim3(DM / 128, BT / 128), 256, GEMM_SMEM>>>(xhi, xlo, wqhi, wqlo, bq, q, BT, DM, DM);
    gemm_mma_split<<<dim3(DL / 128, BT / 128), 256, GEMM_SMEM>>>(xhi, xlo, wkdhi, wkdlo, bkd,
                                                                 kvdhi, kvdlo, BT, DL, DM);
    gemm_mma<<<dim3(2 * DM / 128, BT / 128), 256, GEMM_SMEM>>>(kvdhi, kvdlo, wkuhi, wkulo, bku, kv, BT, 2 * DM, DL);

    rope_transpose<<<BT, 512>>>(q, kv, qh, kh, qbhi, qblo, kbhi, kblo, vbhi, vblo);
    mean_kv<<<BHN, 512>>>(kh, vbhi, vblo, mk, mv);

    flash_mma<<<dim3(TT / 128, BHN), 256, FLASH_SMEM>>>(qbhi, qblo, kbhi, kblo, vbhi, vblo,
                                                        bt, qh, mk, mv, ctxhi, ctxlo);

    gemm_mma<<<dim3(DM / 128, BT / 128), 256, GEMM_SMEM>>>(ctxhi, ctxlo, wohi, wolo, bo, out, BT, DM, DM);
}

// round 17
// speedup vs baseline: 1.0090x; 1.0090x over previous
#include <cuda_runtime.h>
#include <cuda_bf16.h>
#include <math.h>
#include <cstdint>

#define NB 2
#define TT 2048
#define BT 4096      // NB*TT
#define NH 16
#define HD 64
#define DM 1024
#define DL 256
#define BHN 32       // NB*NH
#define LOG2E 1.4426950408889634f

// ---------------- static device scratch ----------------
__device__ float g_q  [BT * DM];
__device__ float g_kv [BT * 2 * DM];
__device__ float g_qh [BHN * TT * HD];
__device__ float g_kh [BHN * TT * HD];
__device__ float g_mk [BHN * HD];
__device__ float g_mv [BHN * HD];
__device__ float g_bias[2 * TT - 1];
__device__ double g_invf[32];

__device__ __nv_bfloat16 g_xhi [BT * DM],  g_xlo [BT * DM];
__device__ __nv_bfloat16 g_kvdhi[BT * DL], g_kvdlo[BT * DL];
__device__ __nv_bfloat16 g_ctxhi[BT * DM], g_ctxlo[BT * DM];
__device__ __nv_bfloat16 g_wqhi [DM * DM],     g_wqlo [DM * DM];
__device__ __nv_bfloat16 g_wkdhi[DL * DM],     g_wkdlo[DL * DM];
__device__ __nv_bfloat16 g_wkuhi[2 * DM * DL], g_wkulo[2 * DM * DL];
__device__ __nv_bfloat16 g_wohi [DM * DM],     g_wolo [DM * DM];
__device__ __nv_bfloat16 g_qbhi[BHN * TT * HD], g_qblo[BHN * TT * HD];   // [bh][t][d]
__device__ __nv_bfloat16 g_kbhi[BHN * TT * HD], g_kblo[BHN * TT * HD];   // [bh][t][d]
__device__ __nv_bfloat16 g_vbhi[BHN * TT * HD], g_vblo[BHN * TT * HD];   // [bh][t][d]

// ---------------- PTX helpers (sm_80-compatible only) ----------------
__device__ __forceinline__ uint32_t smem_u32(const void* p) {
    uint32_t a;
    asm("{ .reg .u64 t; cvta.to.shared.u64 t, %1; cvt.u32.u64 %0, t; }" : "=r"(a) : "l"(p));
    return a;
}
__device__ __forceinline__ void cp16(uint32_t dst, const void* src) {
    asm volatile("cp.async.cg.shared.global [%0], [%1], 16;" :: "r"(dst), "l"(src));
}
#define CP_COMMIT() asm volatile("cp.async.commit_group;" ::: "memory")
#define CP_WAIT(n)  asm volatile("cp.async.wait_group %0;" :: "n"(n) : "memory")

__device__ __forceinline__ void ldsm4(uint32_t* r, uint32_t addr) {
    asm volatile("ldmatrix.sync.aligned.m8n8.x4.shared.b16 {%0,%1,%2,%3}, [%4];"
        : "=r"(r[0]), "=r"(r[1]), "=r"(r[2]), "=r"(r[3]) : "r"(addr));
}
__device__ __forceinline__ void ldsm4t(uint32_t* r, uint32_t addr) {
    asm volatile("ldmatrix.sync.aligned.m8n8.x4.trans.shared.b16 {%0,%1,%2,%3}, [%4];"
        : "=r"(r[0]), "=r"(r[1]), "=r"(r[2]), "=r"(r[3]) : "r"(addr));
}
__device__ __forceinline__ void mma_bf16(float* d, const uint32_t* a, uint32_t b0, uint32_t b1) {
    asm volatile("mma.sync.aligned.m16n8k16.row.col.f32.bf16.bf16.f32 "
        "{%0,%1,%2,%3},{%4,%5,%6,%7},{%8,%9},{%0,%1,%2,%3};"
        : "+f"(d[0]), "+f"(d[1]), "+f"(d[2]), "+f"(d[3])
        : "r"(a[0]), "r"(a[1]), "r"(a[2]), "r"(a[3]), "r"(b0), "r"(b1));
}
__device__ __forceinline__ uint32_t pack_bf2(float a, float b) {
    __nv_bfloat162 h = __float22bfloat162_rn(make_float2(a, b));
    return *reinterpret_cast<uint32_t*>(&h);
}

// ---------------- conversion kernels ----------------
__global__ void conv_split(const float* __restrict__ in, __nv_bfloat16* __restrict__ hi,
                           __nv_bfloat16* __restrict__ lo, int n) {
    int i = (blockIdx.x * blockDim.x + threadIdx.x) * 4;
    if (i >= n) return;
    float4 v = *(const float4*)(in + i);
    float f[4] = {v.x, v.y, v.z, v.w};
    __nv_bfloat16 h[4], l[4];
    #pragma unroll
    for (int j = 0; j < 4; j++) {
        h[j] = __float2bfloat16_rn(f[j]);
        l[j] = __float2bfloat16_rn(f[j] - __bfloat162float(h[j]));
    }
    *(__nv_bfloat162*)(hi + i)     = __nv_bfloat162(h[0], h[1]);
    *(__nv_bfloat162*)(hi + i + 2) = __nv_bfloat162(h[2], h[3]);
    *(__nv_bfloat162*)(lo + i)     = __nv_bfloat162(l[0], l[1]);
    *(__nv_bfloat162*)(lo + i + 2) = __nv_bfloat162(l[2], l[3]);
}

// W[K,N] -> hiT/loT[N,K]
__global__ void transpose_split(const float* __restrict__ in, __nv_bfloat16* __restrict__ hiT,
                                __nv_bfloat16* __restrict__ loT, int K, int N) {
    __shared__ float t[32][33];
    int n0 = blockIdx.x * 32, k0 = blockIdx.y * 32;
    int tx = threadIdx.x, ty = threadIdx.y;  // 32 x 8
    #pragma unroll
    for (int j = 0; j < 32; j += 8)
        t[ty + j][tx] = in[(size_t)(k0 + ty + j) * N + n0 + tx];
    __syncthreads();
    #pragma unroll
    for (int j = 0; j < 32; j += 8) {
        float f = t[tx][ty + j];
        __nv_bfloat16 h = __float2bfloat16_rn(f);
        __nv_bfloat16 l = __float2bfloat16_rn(f - __bfloat162float(h));
        hiT[(size_t)(n0 + ty + j) * K + k0 + tx] = h;
        loT[(size_t)(n0 + ty + j) * K + k0 + tx] = l;
    }
}

// ---------------- mma.sync GEMM mainloop (BK=32, PITCH 80, 2-stage — validated best) ----------------
#define PITCH 80
#define TILEB 10240
#define STAGEB 40960

#define GEMM_MAINLOOP(Ahi, Alo, Bhi, Blo, K)                                              \
    float acc[2][8][4];                                                                   \
    _Pragma("unroll")                                                                     \
    for (int a_ = 0; a_ < 2; a_++)                                                        \
        _Pragma("unroll")                                                                 \
        for (int b_ = 0; b_ < 8; b_++)                                                    \
            _Pragma("unroll")                                                             \
            for (int c_ = 0; c_ < 4; c_++) acc[a_][b_][c_] = 0.f;                         \
    int lrow = tid >> 1;                                                                  \
    int lc0 = (tid & 1) * 2;                                                              \
    auto load_stage = [&](int kb, int st) {                                               \
        size_t gA = (size_t)(m0 + lrow) * (K) + kb * 32 + lc0 * 8;                        \
        size_t gB = (size_t)(n0 + lrow) * (K) + kb * 32 + lc0 * 8;                        \
        uint32_t so = smb + st * STAGEB + lrow * PITCH + lc0 * 16;                        \
        cp16(so,                  Ahi + gA); cp16(so + 16,              Ahi + gA + 8);    \
        cp16(so + TILEB,          Alo + gA); cp16(so + TILEB + 16,      Alo + gA + 8);    \
        cp16(so + 2 * TILEB,      Bhi + gB); cp16(so + 2 * TILEB + 16,  Bhi + gB + 8);    \
        cp16(so + 3 * TILEB,      Blo + gB); cp16(so + 3 * TILEB + 16,  Blo + gB + 8);    \
    };                                                                                    \
    const int NBK = (K) >> 5;                                                             \
    load_stage(0, 0);                                                                     \
    CP_COMMIT();                                                                          \
    for (int kb = 0; kb < NBK; kb++) {                                                    \
        int st = kb & 1;                                                                  \
        if (kb + 1 < NBK) { load_stage(kb + 1, st ^ 1); CP_COMMIT(); CP_WAIT(1); }        \
        else             { CP_WAIT(0); }                                                 \
        __syncthreads();                                                                  \
        uint32_t base = smb + st * STAGEB;                                                \
        _Pragma("unroll")                                                                 \
        for (int s16 = 0; s16 < 2; s16++) {                                               \
            uint32_t koff = s16 * 32;                                                     \
            uint32_t ah[2][4], al[2][4];                                                  \
            _Pragma("unroll")                                                             \
            for (int mf = 0; mf < 2; mf++) {                                              \
                uint32_t ad = base + (wm + mf * 16 + (lane & 15)) * PITCH + koff + (lane >> 4) * 16; \
                ldsm4(ah[mf], ad);                                                        \
                ldsm4(al[mf], ad + TILEB);                                                \
            }                                                                             \
            uint32_t bhf[8][2], blf[8][2];                                                \
            _Pragma("unroll")                                                             \
            for (int nb = 0; nb < 4; nb++) {                                              \
                uint32_t bd = base + 2 * TILEB + (wn + nb * 16 + (lane & 15)) * PITCH + koff + (lane >> 4) * 16; \
                uint32_t r[4];                                                            \
                ldsm4(r, bd);                                                             \
                bhf[2 * nb][0] = r[0]; bhf[2 * nb][1] = r[2];                             \
                bhf[2 * nb + 1][0] = r[1]; bhf[2 * nb + 1][1] = r[3];                     \
                ldsm4(r, bd + TILEB);                                                     \
                blf[2 * nb][0] = r[0]; blf[2 * nb][1] = r[2];                             \
                blf[2 * nb + 1][0] = r[1]; blf[2 * nb + 1][1] = r[3];                     \
            }                                                                             \
            _Pragma("unroll")                                                             \
            for (int mf = 0; mf < 2; mf++)                                                \
                _Pragma("unroll")                                                         \
                for (int nf = 0; nf < 8; nf++) {                                          \
                    mma_bf16(acc[mf][nf], ah[mf], bhf[nf][0], bhf[nf][1]);                \
                    mma_bf16(acc[mf][nf], ah[mf], blf[nf][0], blf[nf][1]);                \
                    mma_bf16(acc[mf][nf], al[mf], bhf[nf][0], bhf[nf][1]);                \
                }                                                                         \
        }                                                                                 \
        __syncthreads();                                                                  \
    }

__global__ void __launch_bounds__(256, 1)
gemm_mma(const __nv_bfloat16* __restrict__ Ahi, const __nv_bfloat16* __restrict__ Alo,
         const __nv_bfloat16* __restrict__ Bhi, const __nv_bfloat16* __restrict__ Blo,
         const float* __restrict__ bias, float* __restrict__ C, int M, int N, int K) {
    extern __shared__ __align__(128) char sm[];
    uint32_t smb = smem_u32(sm);
    int tid = threadIdx.x, lane = tid & 31, wid = tid >> 5;
    int m0 = blockIdx.y * 128, n0 = blockIdx.x * 128;
    int wm = (wid & 3) * 32, wn = (wid >> 2) * 64;

    GEMM_MAINLOOP(Ahi, Alo, Bhi, Blo, K)

    #pragma unroll
    for (int mf = 0; mf < 2; mf++) {
        int r0 = m0 + wm + mf * 16 + (lane >> 2);
        #pragma unroll
        for (int nf = 0; nf < 8; nf++) {
            int c0 = n0 + wn + nf * 8 + (lane & 3) * 2;
            float2 v0, v1;
            v0.x = acc[mf][nf][0] + bias[c0];
            v0.y = acc[mf][nf][1] + bias[c0 + 1];
            v1.x = acc[mf][nf][2] + bias[c0];
            v1.y = acc[mf][nf][3] + bias[c0 + 1];
            *(float2*)&C[(size_t)r0 * N + c0]       = v0;
            *(float2*)&C[(size_t)(r0 + 8) * N + c0] = v1;
        }
    }
}

// same mainloop, bf16-split output (for KV-down projection)
__global__ void __launch_bounds__(256, 1)
gemm_mma_split(const __nv_bfloat16* __restrict__ Ahi, const __nv_bfloat16* __restrict__ Alo,
               const __nv_bfloat16* __restrict__ Bhi, const __nv_bfloat16* __restrict__ Blo,
               const float* __restrict__ bias, __nv_bfloat16* __restrict__ Chi,
               __nv_bfloat16* __restrict__ Clo, int M, int N, int K) {
    extern __shared__ __align__(128) char sm[];
    uint32_t smb = smem_u32(sm);
    int tid = threadIdx.x, lane = tid & 31, wid = tid >> 5;
    int m0 = blockIdx.y * 128, n0 = blockIdx.x * 128;
    int wm = (wid & 3) * 32, wn = (wid >> 2) * 64;

    GEMM_MAINLOOP(Ahi, Alo, Bhi, Blo, K)

    #pragma unroll
    for (int mf = 0; mf < 2; mf++) {
        int r0 = m0 + wm + mf * 16 + (lane >> 2);
        #pragma unroll
        for (int nf = 0; nf < 8; nf++) {
            int c0 = n0 + wn + nf * 8 + (lane & 3) * 2;
            #pragma unroll
            for (int half = 0; half < 2; half++) {
                float f0 = acc[mf][nf][half * 2]     + bias[c0];
                float f1 = acc[mf][nf][half * 2 + 1] + bias[c0 + 1];
                __nv_bfloat16 h0 = __float2bfloat16_rn(f0), h1 = __float2bfloat16_rn(f1);
                __nv_bfloat16 l0 = __float2bfloat16_rn(f0 - __bfloat162float(h0));
                __nv_bfloat16 l1 = __float2bfloat16_rn(f1 - __bfloat162float(h1));
                size_t off = (size_t)(r0 + half * 8) * N + c0;
                *(__nv_bfloat162*)&Chi[off] = __nv_bfloat162(h0, h1);
                *(__nv_bfloat162*)&Clo[off] = __nv_bfloat162(l0, l1);
            }
        }
    }
}

// ---------------- bias table (pre-scaled by log2 e) + inv_freq table ----------------
__global__ void bias_table(float* __restrict__ bt) {
    int idx = blockIdx.x * blockDim.x + threadIdx.x;
    if (idx < 32)
        g_invf[idx] = pow(10000.0, -(double)idx / 32.0);
    if (idx < 2 * TT - 1) {
        float d = (float)(idx - (TT - 1));
        float ls = -0.1f * logf(fabsf(d) + 1.0f);
        float dec = expf(-fmaxf(d, 0.0f) * 0.01f);
        bt[idx] = (ls + logf(dec + 1e-9f)) * LOG2E;
    }
}

// ---------------- RoPE + transpose (+ bf16 splits q,k,v) ----------------
__global__ void rope_transpose(const float* __restrict__ q, const float* __restrict__ kv,
                               float* __restrict__ qh, float* __restrict__ kh,
                               __nv_bfloat16* __restrict__ qbhi, __nv_bfloat16* __restrict__ qblo,
                               __nv_bfloat16* __restrict__ kbhi, __nv_bfloat16* __restrict__ kblo,
                               __nv_bfloat16* __restrict__ vbhi, __nv_bfloat16* __restrict__ vblo) {
    int token = blockIdx.x;
    int b = token / TT, t = token % TT;
    int tid = threadIdx.x;
    int h = tid >> 5, i = tid & 31;

    float ang = (float)((double)t * g_invf[i]);
    float cf = cosf(ang);
    float sf = sinf(ang);

    size_t dst = ((size_t)(b * NH + h) * TT + t) * HD;
    {
        const float* src = q + (size_t)token * DM + h * HD;
        float x1 = src[i], x2 = src[i + 32];
        float r1 = x1 * cf - x2 * sf;
        float r2 = x1 * sf + x2 * cf;
        qh[dst + i]      = r1;
        qh[dst + i + 32] = r2;
        __nv_bfloat16 h1 = __float2bfloat16_rn(r1), h2 = __float2bfloat16_rn(r2);
        qbhi[dst + i] = h1;      qblo[dst + i]      = __float2bfloat16_rn(r1 - __bfloat162float(h1));
        qbhi[dst + i + 32] = h2; qblo[dst + i + 32] = __float2bfloat16_rn(r2 - __bfloat162float(h2));
    }
    {
        const float* src = kv + (size_t)token * (2 * DM) + h * (2 * HD);
        float x1 = src[i], x2 = src[i + 32];
        float r1 = x1 * cf - x2 * sf;
        float r2 = x1 * sf + x2 * cf;
        kh[dst + i]      = r1;
        kh[dst + i + 32] = r2;
        __nv_bfloat16 h1 = __float2bfloat16_rn(r1), h2 = __float2bfloat16_rn(r2);
        kbhi[dst + i] = h1;      kblo[dst + i]      = __float2bfloat16_rn(r1 - __bfloat162float(h1));
        kbhi[dst + i + 32] = h2; kblo[dst + i + 32] = __float2bfloat16_rn(r2 - __bfloat162float(h2));
        float v1 = src[64 + i], v2 = src[64 + i + 32];
        __nv_bfloat16 vh1 = __float2bfloat16_rn(v1), vh2 = __float2bfloat16_rn(v2);
        vbhi[dst + i] = vh1;      vblo[dst + i]      = __float2bfloat16_rn(v1 - __bfloat162float(vh1));
        vbhi[dst + i + 32] = vh2; vblo[dst + i + 32] = __float2bfloat16_rn(v2 - __bfloat162float(vh2));
    }
}

// ---------------- mean-pool (512 threads, 8-way t-split; v from bf16 split) ----------------
__global__ void mean_kv(const float* __restrict__ kh,
                        const __nv_bfloat16* __restrict__ vbhi, const __nv_bfloat16* __restrict__ vblo,
                        float* __restrict__ mk, float* __restrict__ mv) {
    __shared__ float sk[8][64], sv[8][64];
    int bh = blockIdx.x;
    int d = threadIdx.x & 63, grp = threadIdx.x >> 6;
    const float* kb = kh + (size_t)bh * TT * HD;
    const __nv_bfloat16* vbh = vbhi + (size_t)bh * TT * HD;
    const __nv_bfloat16* vbl = vblo + (size_t)bh * TT * HD;
    float a = 0.f, c = 0.f;
    int t0 = grp * (TT / 8), t1 = t0 + TT / 8;
    for (int t = t0; t < t1; t++) {
        a += kb[(size_t)t * HD + d];
        c += __bfloat162float(vbh[(size_t)t * HD + d]) + __bfloat162float(vbl[(size_t)t * HD + d]);
    }
    sk[grp][d] = a;
    sv[grp][d] = c;
    __syncthreads();
    if (grp == 0) {
        float ta = 0.f, tc = 0.f;
        #pragma unroll
        for (int g = 0; g < 8; g++) { ta += sk[g][d]; tc += sv[g][d]; }
        mk[bh * HD + d] = ta * (1.0f / TT);
        mv[bh * HD + d] = tc * (1.0f / TT);
    }
}

// ---------------- flash attention: BM=128 BN=64, 6-stage ring, sync per 2 iters ----------------
#define FPITCH 144
#define FTILE  (64 * FPITCH)   // 9216
#define FSTG   (4 * FTILE)     // 36864 per stage (Khi|Klo|Vhi|Vlo, all [t][d])
#define NSTG   6
__global__ void __launch_bounds__(256, 1)
flash_mma(const __nv_bfloat16* __restrict__ qbhi, const __nv_bfloat16* __restrict__ qblo,
          const __nv_bfloat16* __restrict__ kbhi, const __nv_bfloat16* __restrict__ kblo,
          const __nv_bfloat16* __restrict__ vbhi, const __nv_bfloat16* __restrict__ vblo,
          const float* __restrict__ bias_tab, const float* __restrict__ qh,
          const float* __restrict__ mk, const float* __restrict__ mv,
          __nv_bfloat16* __restrict__ ctxhi, __nv_bfloat16* __restrict__ ctxlo) {
    extern __shared__ __align__(128) char sm[];
    __shared__ float mks[64], mvs[64];
    uint32_t smb = smem_u32(sm);
    int tid = threadIdx.x, lane = tid & 31, wid = tid >> 5;
    int bh = blockIdx.y, q0 = blockIdx.x * 128;
    int b = bh >> 4, h = bh & 15;
    int wm = wid * 16;

    const __nv_bfloat16* qhB = qbhi + (size_t)bh * TT * HD;
    const __nv_bfloat16* qlB = qblo + (size_t)bh * TT * HD;
    const __nv_bfloat16* khB = kbhi + (size_t)bh * TT * HD;
    const __nv_bfloat16* klB = kblo + (size_t)bh * TT * HD;
    const __nv_bfloat16* vhB = vbhi + (size_t)bh * TT * HD;
    const __nv_bfloat16* vlB = vblo + (size_t)bh * TT * HD;

    if (tid < 64) mks[tid] = mk[bh * HD + tid];
    else if (tid < 128) mvs[tid - 64] = mv[bh * HD + tid - 64];

    // ---- stage Q (128 x 64 bf16 hi+lo) into stage-0 area, extract frags ----
    {
        int row = tid >> 1;
        int ch  = (tid & 1) * 4;
        size_t g = (size_t)(q0 + row) * HD + ch * 8;
        uint32_t so = smb + row * FPITCH + ch * 16;
        #pragma unroll
        for (int c = 0; c < 4; c++) {
            cp16(so + c * 16,             qhB + g + c * 8);
            cp16(so + 2 * FTILE + c * 16, qlB + g + c * 8);
        }
    }
    CP_COMMIT(); CP_WAIT(0);
    __syncthreads();

    uint32_t qfh[4][4], qfl[4][4];
    #pragma unroll
    for (int ks = 0; ks < 4; ks++) {
        uint32_t ad = smb + (wm + (lane & 15)) * FPITCH + ks * 32 + (lane >> 4) * 16;
        ldsm4(qfh[ks], ad);
        ldsm4(qfl[ks], ad + 2 * FTILE);
    }
    __syncthreads();

    float o[8][4];
    #pragma unroll
    for (int i = 0; i < 8; i++)
        #pragma unroll
        for (int j = 0; j < 4; j++) o[i][j] = 0.f;
    float miA = -1e30f, miB = -1e30f, liA = 0.f, liB = 0.f;

    auto load_stage = [&](int k0, int st) {
        int row = tid >> 2;
        int ch  = (tid & 3) * 2;
        uint32_t so = smb + st * FSTG + row * FPITCH + ch * 16;
        size_t gk = (size_t)(k0 + row) * HD + ch * 8;
        cp16(so,             khB + gk); cp16(so + 16,             khB + gk + 8);
        cp16(so + FTILE,     klB + gk); cp16(so + FTILE + 16,     klB + gk + 8);
        cp16(so + 2 * FTILE, vhB + gk); cp16(so + 2 * FTILE + 16, vhB + gk + 8);
        cp16(so + 3 * FTILE, vlB + gk); cp16(so + 3 * FTILE + 16, vlB + gk + 8);
    };

    const float SC = 0.125f * LOG2E;
    const int NKB = TT / 64;
    int vrow = (lane & 7) + ((lane >> 4) & 1) * 8;
    int vcol = ((lane >> 3) & 1) * 16;

    auto body = [&](int kb) {
        int k0 = kb * 64;
        uint32_t kb_s = smb + (kb % NSTG) * FSTG;
        uint32_t vb_s = kb_s + 2 * FTILE;

        float s[8][4];
        #pragma unroll
        for (int i = 0; i < 8; i++)
            #pragma unroll
            for (int j = 0; j < 4; j++) s[i][j] = 0.f;

        #pragma unroll
        for (int ks = 0; ks < 4; ks++) {
            #pragma unroll
            for (int g = 0; g < 4; g++) {
                uint32_t ad = kb_s + (16 * g + (lane & 15)) * FPITCH + ks * 32 + (lane >> 4) * 16;
                uint32_t rh[4], rl[4];
                ldsm4(rh, ad);
                ldsm4(rl, ad + FTILE);
                mma_bf16(s[2 * g],     qfh[ks], rh[0], rh[2]);
                mma_bf16(s[2 * g],     qfh[ks], rl[0], rl[2]);
                mma_bf16(s[2 * g],     qfl[ks], rh[0], rh[2]);
                mma_bf16(s[2 * g + 1], qfh[ks], rh[1], rh[3]);
                mma_bf16(s[2 * g + 1], qfh[ks], rl[1], rl[3]);
                mma_bf16(s[2 * g + 1], qfl[ks], rh[1], rh[3]);
            }
        }

        int rA = wm + (lane >> 2);
        const float* bp = bias_tab + (q0 - k0 + rA - (lane & 3) * 2 + (TT - 1));
        float rmaxA = -1e30f, rmaxB = -1e30f;
        #pragma unroll
        for (int nf = 0; nf < 8; nf++) {
            s[nf][0] = s[nf][0] * SC + __ldg(bp - 8 * nf);
            s[nf][1] = s[nf][1] * SC + __ldg(bp - 8 * nf - 1);
            s[nf][2] = s[nf][2] * SC + __ldg(bp - 8 * nf + 8);
            s[nf][3] = s[nf][3] * SC + __ldg(bp - 8 * nf + 7);
            rmaxA = fmaxf(rmaxA, fmaxf(s[nf][0], s[nf][1]));
            rmaxB = fmaxf(rmaxB, fmaxf(s[nf][2], s[nf][3]));
        }
        #pragma unroll
        for (int off = 1; off <= 2; off <<= 1) {
            rmaxA = fmaxf(rmaxA, __shfl_xor_sync(0xffffffffu, rmaxA, off));
            rmaxB = fmaxf(rmaxB, __shfl_xor_sync(0xffffffffu, rmaxB, off));
        }
        float mnA = fmaxf(miA, rmaxA), mnB = fmaxf(miB, rmaxB);
        float scA = exp2f(miA - mnA), scB = exp2f(miB - mnB);
        miA = mnA; miB = mnB;
        float rsA = 0.f, rsB = 0.f;
        #pragma unroll
        for (int nf = 0; nf < 8; nf++) {
            s[nf][0] = exp2f(s[nf][0] - mnA);
            s[nf][1] = exp2f(s[nf][1] - mnA);
            s[nf][2] = exp2f(s[nf][2] - mnB);
            s[nf][3] = exp2f(s[nf][3] - mnB);
            rsA += s[nf][0] + s[nf][1];
            rsB += s[nf][2] + s[nf][3];
        }
        #pragma unroll
        for (int off = 1; off <= 2; off <<= 1) {
            rsA += __shfl_xor_sync(0xffffffffu, rsA, off);
            rsB += __shfl_xor_sync(0xffffffffu, rsB, off);
        }
        liA = liA * scA + rsA;
        liB = liB * scB + rsB;
        #pragma unroll
        for (int i = 0; i < 8; i++) {
            o[i][0] *= scA; o[i][1] *= scA;
            o[i][2] *= scB; o[i][3] *= scB;
        }

        #pragma unroll
        for (int ks = 0; ks < 4; ks++) {
            uint32_t ah[4], al[4];
            {
                float* p0 = s[2 * ks];
                float* p1 = s[2 * ks + 1];
                ah[0] = pack_bf2(p0[0], p0[1]);
                ah[1] = pack_bf2(p0[2], p0[3]);
                ah[2] = pack_bf2(p1[0], p1[1]);
                ah[3] = pack_bf2(p1[2], p1[3]);
                __nv_bfloat162* h0 = (__nv_bfloat162*)&ah[0];
                __nv_bfloat162* h1 = (__nv_bfloat162*)&ah[1];
                __nv_bfloat162* h2 = (__nv_bfloat162*)&ah[2];
                __nv_bfloat162* h3 = (__nv_bfloat162*)&ah[3];
                al[0] = pack_bf2(p0[0] - __bfloat162float(h0->x), p0[1] - __bfloat162float(h0->y));
                al[1] = pack_bf2(p0[2] - __bfloat162float(h1->x), p0[3] - __bfloat162float(h1->y));
                al[2] = pack_bf2(p1[0] - __bfloat162float(h2->x), p1[1] - __bfloat162float(h2->y));
                al[3] = pack_bf2(p1[2] - __bfloat162float(h3->x), p1[3] - __bfloat162float(h3->y));
            }
            #pragma unroll
            for (int g = 0; g < 4; g++) {
                uint32_t ad = vb_s + (ks * 16 + vrow) * FPITCH + g * 32 + vcol;
                uint32_t rh[4], rl[4];
                ldsm4t(rh, ad);
                ldsm4t(rl, ad + FTILE);
                mma_bf16(o[2 * g],     ah, rh[0], rh[2]);
                mma_bf16(o[2 * g],     al, rh[0], rh[2]);
                mma_bf16(o[2 * g],     ah, rl[0], rl[2]);
                mma_bf16(o[2 * g + 1], ah, rh[1], rh[3]);
                mma_bf16(o[2 * g + 1], al, rh[1], rh[3]);
                mma_bf16(o[2 * g + 1], ah, rl[1], rl[3]);
            }
        }
    };

    // prologue: stages 0..3
    load_stage(0, 0);       CP_COMMIT();
    load_stage(64, 1);      CP_COMMIT();
    load_stage(128, 2);     CP_COMMIT();
    load_stage(192, 3);     CP_COMMIT();

    for (int kb = 0; kb < NKB; kb += 2) {
        __syncthreads();
        if (kb + 4 < NKB) { load_stage((kb + 4) * 64, (kb + 4) % NSTG); CP_COMMIT(); }
        if (kb + 5 < NKB) { load_stage((kb + 5) * 64, (kb + 5) % NSTG); CP_COMMIT(); }
        if (kb + 6 <= NKB)      { CP_WAIT(4); }
        else if (kb + 4 <= NKB) { CP_WAIT(2); }
        else                    { CP_WAIT(0); }
        body(kb);
        body(kb + 1);
    }

    // ---- epilogue: normalize + fused infini + bf16 split write ----
    float invA = 1.0f / liA, invB = 1.0f / liB;
    int rowA = q0 + wm + (lane >> 2);
    const float* qrowA = qh + ((size_t)bh * TT + rowA) * HD;
    const float* qrowB = qrowA + 8 * HD;
    float dA = 0.f, dB = 0.f;
    #pragma unroll
    for (int j = 0; j < 16; j++) {
        int d = (lane & 3) * 16 + j;
        dA += qrowA[d] * mks[d];
        dB += qrowB[d] * mks[d];
    }
    #pragma unroll
    for (int off = 1; off <= 2; off <<= 1) {
        dA += __shfl_xor_sync(0xffffffffu, dA, off);
        dB += __shfl_xor_sync(0xffffffffu, dB, off);
    }
    float gA = 0.2f / (1.0f + expf(-dA));
    float gB = 0.2f / (1.0f + expf(-dB));

    #pragma unroll
    for (int nf = 0; nf < 8; nf++) {
        int c0 = 8 * nf + (lane & 3) * 2;
        float f[4];
        f[0] = o[nf][0] * invA + gA * mvs[c0];
        f[1] = o[nf][1] * invA + gA * mvs[c0 + 1];
        f[2] = o[nf][2] * invB + gB * mvs[c0];
        f[3] = o[nf][3] * invB + gB * mvs[c0 + 1];
        __nv_bfloat16 h0 = __float2bfloat16_rn(f[0]), h1 = __float2bfloat16_rn(f[1]);
        __nv_bfloat16 h2 = __float2bfloat16_rn(f[2]), h3 = __float2bfloat16_rn(f[3]);
        __nv_bfloat16 l0 = __float2bfloat16_rn(f[0] - __bfloat162float(h0));
        __nv_bfloat16 l1 = __float2bfloat16_rn(f[1] - __bfloat162float(h1));
        __nv_bfloat16 l2 = __float2bfloat16_rn(f[2] - __bfloat162float(h2));
        __nv_bfloat16 l3 = __float2bfloat16_rn(f[3] - __bfloat162float(h3));
        size_t oA = ((size_t)b * TT + rowA) * DM + h * HD + c0;
        size_t oB = ((size_t)b * TT + rowA + 8) * DM + h * HD + c0;
        *(__nv_bfloat162*)&ctxhi[oA] = __nv_bfloat162(h0, h1);
        *(__nv_bfloat162*)&ctxlo[oA] = __nv_bfloat162(l0, l1);
        *(__nv_bfloat162*)&ctxhi[oB] = __nv_bfloat162(h2, h3);
        *(__nv_bfloat162*)&ctxlo[oB] = __nv_bfloat162(l2, l3);
    }
}

// ---------------- launcher ----------------
extern "C" void kernel_launch(void* const* d_in, const int* in_sizes, int n_in,
                              void* d_out, int out_size) {
    const float* x   = (const float*)d_in[0];
    const float* Wq  = (const float*)d_in[1];
    const float* bq  = (const float*)d_in[2];
    const float* Wkd = (const float*)d_in[3];
    const float* bkd = (const float*)d_in[4];
    const float* Wku = (const float*)d_in[5];
    const float* bku = (const float*)d_in[6];
    const float* Wo  = (const float*)d_in[7];
    const float* bo  = (const float*)d_in[8];
    float* out = (float*)d_out;

    float *q, *kv, *qh, *kh, *mk, *mv, *bt;
    cudaGetSymbolAddress((void**)&q,   g_q);
    cudaGetSymbolAddress((void**)&kv,  g_kv);
    cudaGetSymbolAddress((void**)&qh,  g_qh);
    cudaGetSymbolAddress((void**)&kh,  g_kh);
    cudaGetSymbolAddress((void**)&mk,  g_mk);
    cudaGetSymbolAddress((void**)&mv,  g_mv);
    cudaGetSymbolAddress((void**)&bt,  g_bias);

    __nv_bfloat16 *xhi, *xlo, *kvdhi, *kvdlo, *ctxhi, *ctxlo;
    __nv_bfloat16 *wqhi, *wqlo, *wkdhi, *wkdlo, *wkuhi, *wkulo, *wohi, *wolo;
    __nv_bfloat16 *qbhi, *qblo, *kbhi, *kblo, *vbhi, *vblo;
    cudaGetSymbolAddress((void**)&xhi,   g_xhi);   cudaGetSymbolAddress((void**)&xlo,   g_xlo);
    cudaGetSymbolAddress((void**)&kvdhi, g_kvdhi); cudaGetSymbolAddress((void**)&kvdlo, g_kvdlo);
    cudaGetSymbolAddress((void**)&ctxhi, g_ctxhi); cudaGetSymbolAddress((void**)&ctxlo, g_ctxlo);
    cudaGetSymbolAddress((void**)&wqhi,  g_wqhi);  cudaGetSymbolAddress((void**)&wqlo,  g_wqlo);
    cudaGetSymbolAddress((void**)&wkdhi, g_wkdhi); cudaGetSymbolAddress((void**)&wkdlo, g_wkdlo);
    cudaGetSymbolAddress((void**)&wkuhi, g_wkuhi); cudaGetSymbolAddress((void**)&wkulo, g_wkulo);
    cudaGetSymbolAddress((void**)&wohi,  g_wohi);  cudaGetSymbolAddress((void**)&wolo,  g_wolo);
    cudaGetSymbolAddress((void**)&qbhi,  g_qbhi);  cudaGetSymbolAddress((void**)&qblo,  g_qblo);
    cudaGetSymbolAddress((void**)&kbhi,  g_kbhi);  cudaGetSymbolAddress((void**)&kblo,  g_kblo);
    cudaGetSymbolAddress((void**)&vbhi,  g_vbhi);  cudaGetSymbolAddress((void**)&vblo,  g_vblo);

    const int GEMM_SMEM = 2 * STAGEB;     // 81920
    cudaFuncSetAttribute(gemm_mma, cudaFuncAttributeMaxDynamicSharedMemorySize, GEMM_SMEM);
    cudaFuncSetAttribute(gemm_mma_split, cudaFuncAttributeMaxDynamicSharedMemorySize, GEMM_SMEM);
    const int FLASH_SMEM = NSTG * FSTG;   // 221184
    cudaFuncSetAttribute(flash_mma, cudaFuncAttributeMaxDynamicSharedMemorySize, FLASH_SMEM);

    dim3 t328(32, 8);

    bias_table<<<(2 * TT - 1 + 255) / 256, 256>>>(bt);

    transpose_split<<<dim3(DM / 32, DM / 32), t328>>>(Wq,  wqhi,  wqlo,  DM, DM);
    transpose_split<<<dim3(DL / 32, DM / 32), t328>>>(Wkd, wkdhi, wkdlo, DM, DL);
    transpose_split<<<dim3(2 * DM / 32, DL / 32), t328>>>(Wku, wkuhi, wkulo, DL, 2 * DM);
    transpose_split<<<dim3(DM / 32, DM / 32), t328>>>(Wo,  wohi,  wolo,  DM, DM);

    conv_split<<<(BT * DM / 4 + 255) / 256, 256>>>(x, xhi, xlo, BT * DM);

    gemm_mma<<<dim3(DM / 128, BT / 128), 256, GEMM_SMEM>>>(xhi, xlo, wqhi, wqlo, bq, q, BT, DM, DM);
    gemm_mma_split<<<dim3(DL / 128, BT / 128), 256, GEMM_SMEM>>>(xhi, xlo, wkdhi, wkdlo, bkd,
                                                                 kvdhi, kvdlo, BT, DL, DM);
    gemm_mma<<<dim3(2 * DM / 128, BT / 128), 256, GEMM_SMEM>>>(kvdhi, kvdlo, wkuhi, wkulo, bku, kv, BT, 2 * DM, DL);

    rope_transpose<<<BT, 512>>>(q, kv, qh, kh, qbhi, qblo, kbhi, kblo, vbhi, vblo);
    mean_kv<<<BHN, 512>>>(kh, vbhi, vblo, mk, mv);

    flash_mma<<<dim3(TT / 128, BHN), 256, FLASH_SMEM>>>(qbhi, qblo, kbhi, kblo, vbhi, vblo,
                                                        bt, qh, mk, mv, ctxhi, ctxlo);

    gemm_mma<<<dim3(DM / 128, BT / 128), 256, GEMM_SMEM>>>(ctxhi, ctxlo, wohi, wolo, bo, out, BT, DM, DM);
}